// round 14
// baseline (speedup 1.0000x reference)
#include <cuda_runtime.h>
#include <cstdint>

// Problem constants
#define NLEN   8192
#define LOGN   13
#define MODES  1024
#define BATCH  32
#define CIN    64
#define COUT   64
#define IROWS  (BATCH*CIN)    // 2048 input rows
#define OROWS  (BATCH*COUT)   // 2048 output rows

// -------- scratch (no allocations allowed; use __device__ globals) --------
__device__ __align__(16) float g_xm  [IROWS*MODES];   // [row=b*64+i][m]
__device__ __align__(16) float g_xmT [MODES*IROWS];   // [m][row]
__device__ __align__(16) float g_wT  [MODES*CIN*COUT];// [m][i*64+o]
__device__ __align__(16) float g_zT  [MODES*OROWS];   // [m][b*64+o]
__device__ __align__(16) float g_z   [OROWS*MODES];   // [row=b*64+o][m]

// GF(2)-linear smem swizzle. k0^=u5^u9, k1^=u6^u10, k2^=u7^u11, k3^=u8, k4^=u8^u12.
__device__ __forceinline__ int swz(int u) {
    int f = ((u >> 5) & 7) ^ ((u >> 9) & 7)
          ^ (((u >> 8) & 1) * 0x18)
          ^ (((u >> 12) & 1) * 0x10);
    return u ^ f;
}
__device__ __forceinline__ int rev9(int t) { return (int)(__brev((unsigned)t) >> 23); }

// Literal cas values
#define RSQ2  0.70710678118654752f
#define C8L   0.92387953251128674f
#define S8L   0.38268343236508977f
#define C16A  0.98078528040323044f   // cos(pi/16)
#define S16A  0.19509032201612827f   // sin(pi/16)
#define C16B  0.83146961230254524f   // cos(3pi/16)
#define S16B  0.55557023301960222f   // sin(3pi/16)
#define THETA0 7.66990393942820615e-4f   // pi/4096
#define PHI0   1.22718463030851251e-2f   // pi/256

// Packed f32x2 helpers (Blackwell)
typedef unsigned long long ull_t;
__device__ __forceinline__ ull_t pack2(float x) {
    ull_t r; asm("mov.b64 %0, {%1, %1};" : "=l"(r) : "f"(x)); return r;
}
__device__ __forceinline__ ull_t fma2(ull_t a, ull_t b, ull_t c) {
    ull_t d; asm("fma.rn.f32x2 %0, %1, %2, %3;" : "=l"(d) : "l"(a), "l"(b), "l"(c));
    return d;
}
__device__ __forceinline__ void unpack2(ull_t v, float& lo, float& hi) {
    asm("mov.b64 {%0, %1}, %2;" : "=f"(lo), "=f"(hi) : "l"(v));
}

// Phase-C twiddles via MUFU + double-angle (no memory traffic).
struct CTw { float c13p, c13m, c12p, c12m, c11p, c11m, c10; };
__device__ __forceinline__ CTw ctw(int t) {
    float s1, c1;
    __sincosf((float)t * THETA0, &s1, &c1);
    CTw w;
    w.c13p = c1 + s1;  w.c13m = c1 - s1;
    float s2 = 2.0f * s1 * c1, c2 = fmaf(-2.0f * s1, s1, 1.0f);
    w.c12p = c2 + s2;  w.c12m = c2 - s2;
    float s4 = 2.0f * s2 * c2, c4 = fmaf(-2.0f * s2, s2, 1.0f);
    w.c11p = c4 + s4;  w.c11m = c4 - s4;
    float s8 = 2.0f * s4 * c4, c8 = fmaf(-2.0f * s4, s4, 1.0f);
    w.c10  = c8 + s8;
    return w;
}

// -------- Phase A stages 1-4: all twiddles are literals ---------------------
__device__ __forceinline__ void stagesA(float r[16]) {
    #pragma unroll
    for (int e = 0; e < 16; e += 2) {
        float o = r[e + 1]; r[e + 1] = r[e] - o; r[e] += o;
    }
    #pragma unroll
    for (int g = 0; g < 16; g += 4)
        #pragma unroll
        for (int e = g; e < g + 2; e++) {
            float o = r[e + 2]; r[e + 2] = r[e] - o; r[e] += o;
        }
    {
        const float c3[4] = {1.0f, 1.41421356237309515f, 1.0f, 0.0f};
        #pragma unroll
        for (int eb = 0; eb < 4; eb++)
            #pragma unroll
            for (int g = 0; g < 16; g += 8) {
                int e = g + eb;
                float o = c3[eb] * r[e + 4]; r[e + 4] = r[e] - o; r[e] += o;
            }
    }
    {
        const float c4[8] = {1.0f, 1.30656296487637653f, 1.41421356237309515f,
                             1.30656296487637653f, 1.0f, 0.54119610014619701f,
                             0.0f, -0.54119610014619701f};
        #pragma unroll
        for (int e = 0; e < 8; e++) {
            float o = c4[e] * r[e + 8]; r[e + 8] = r[e] - o; r[e] += o;
        }
    }
}

// -------- Phase B stages 5-9: ALL twiddles from MUFU + literals -------------
__device__ __forceinline__ void phaseB(float* sm, float r[16], int t) {
    const int wid  = t >> 5;
    const int lane = t & 31;
    const int base = (lane << 8) | wid;

    float s1, c1;
    __sincosf((float)wid * PHI0, &s1, &c1);
    float p1 = c1 + s1, m1 = c1 - s1;
    float s2 = 2.0f * s1 * c1, c2 = fmaf(-2.0f * s1, s1, 1.0f);
    float p2 = c2 + s2, m2 = c2 - s2;
    float s4 = 2.0f * s2 * c2, c4 = fmaf(-2.0f * s2, s2, 1.0f);
    float p4 = c4 + s4, m4 = c4 - s4;
    float s8 = 2.0f * s4 * c4, c8 = fmaf(-2.0f * s4, s4, 1.0f);
    float p8 = c8 + s8, m8 = c8 - s8;
    float s16 = 2.0f * s8 * c8, c16 = fmaf(-2.0f * s8, s8, 1.0f);
    float p16 = c16 + s16;

    #pragma unroll
    for (int s = 0; s < 16; s++) r[s] = sm[swz(base | (s << 4))];
    #pragma unroll
    for (int s = 0; s < 16; s += 2) {
        float o = p16 * r[s + 1]; r[s + 1] = r[s] - o; r[s] += o;
    }
    {
        const float w6[2] = { p8, m8 };
        #pragma unroll
        for (int sb = 0; sb < 2; sb++)
            #pragma unroll
            for (int g = 0; g < 16; g += 4) {
                int s = g + sb;
                float o = w6[sb] * r[s + 2]; r[s + 2] = r[s] - o; r[s] += o;
            }
    }
    {
        const float w7[4] = { p4, RSQ2 * (p4 + m4), m4, RSQ2 * (m4 - p4) };
        #pragma unroll
        for (int sb = 0; sb < 4; sb++)
            #pragma unroll
            for (int g = 0; g < 16; g += 8) {
                int s = g + sb;
                float o = w7[sb] * r[s + 4]; r[s + 4] = r[s] - o; r[s] += o;
            }
    }
    {
        const float CS[8] = {1.0f, C8L, RSQ2, S8L, 0.0f, -S8L, -RSQ2, -C8L};
        const float SN[8] = {0.0f, S8L, RSQ2, C8L, 1.0f,  C8L,  RSQ2,  S8L};
        #pragma unroll
        for (int s = 0; s < 8; s++) {
            float cas = CS[s] * p2 + SN[s] * m2;
            float o = cas * r[s + 8]; r[s + 8] = r[s] - o; r[s] += o;
        }
    }
    {
        const float CS[16] = { 1.0f,  C16A,  C8L,   C16B,  RSQ2,  S16B,  S8L,   S16A,
                               0.0f, -S16A, -S8L,  -S16B, -RSQ2, -C16B, -C8L,  -C16A};
        const float SN[16] = { 0.0f,  S16A,  S8L,   S16B,  RSQ2,  C16B,  C8L,   C16A,
                               1.0f,  C16A,  C8L,   C16B,  RSQ2,  S16B,  S8L,   S16A};
        const bool odd = (lane & 1);
        #pragma unroll
        for (int s = 0; s < 16; s++) {
            float cas = CS[s] * p1 + SN[s] * m1;
            float p = __shfl_xor_sync(0xFFFFFFFFu, r[s], 1);
            r[s] = odd ? (p - cas * r[s]) : fmaf(cas, p, r[s]);
        }
    }
    #pragma unroll
    for (int s = 0; s < 16; s++) sm[swz(base | (s << 4))] = r[s];
}

// -------- forward: x[row][0..8192) -> xm[row][0..1024) ----------------------
__global__ __launch_bounds__(512, 2) void fht_fwd_kernel(const float* __restrict__ x) {
    __shared__ float sm[NLEN];
    const int row = blockIdx.x;
    const int t = threadIdx.x;
    const float* __restrict__ xr = x + (size_t)row * NLEN;

    float r[16];
    {
        const int REV4[16] = {0,8,4,12, 2,10,6,14, 1,9,5,13, 3,11,7,15};
        #pragma unroll
        for (int e = 0; e < 16; e++) r[REV4[e]] = xr[e * 512 + t];
        stagesA(r);
        const int ub = rev9(t) << 4;
        #pragma unroll
        for (int e = 0; e < 16; e++) sm[swz(ub | e)] = r[e];
    }
    __syncthreads();

    phaseB(sm, r, t);
    __syncthreads();

    {
        CTw w = ctw(t);
        #pragma unroll
        for (int s = 0; s < 16; s++) r[s] = sm[swz((s << 9) | t)];
        #pragma unroll
        for (int s = 0; s < 16; s += 2) {
            float o = w.c10 * r[s + 1]; r[s + 1] = r[s] - o; r[s] += o;
        }
        {
            const float w11[2] = { w.c11p, w.c11m };
            #pragma unroll
            for (int g = 0; g < 16; g += 4)
                #pragma unroll
                for (int sb = 0; sb < 2; sb++)
                    r[g + sb] += w11[sb] * r[g + sb + 2];
        }
        {
            const float w12[2] = { w.c12p, RSQ2 * (w.c12p + w.c12m) };
            #pragma unroll
            for (int g = 0; g < 16; g += 8)
                #pragma unroll
                for (int sb = 0; sb < 2; sb++)
                    r[g + sb] += w12[sb] * r[g + sb + 4];
        }
        r[0] += w.c13p * r[8];
        r[1] += (C8L * w.c13p + S8L * w.c13m) * r[9];

        float* __restrict__ xmr = g_xm + (size_t)row * MODES;
        xmr[t]       = r[0];
        xmr[t + 512] = r[1];
    }
}

// -------- inverse: z[row][0..1024) zero-padded -> out[row][0..8192)/8192 ----
__global__ __launch_bounds__(512, 2) void fht_inv_kernel(float* __restrict__ out) {
    __shared__ float sm[NLEN];
    const int row = blockIdx.x;
    const int t = threadIdx.x;
    const float* __restrict__ zr = g_z + (size_t)row * MODES;

    {
        float v0 = zr[t];
        float v1 = zr[t + 512];
        const int ub = rev9(t) << 4;
        const float c4[8] = {1.0f, 1.30656296487637653f, 1.41421356237309515f,
                             1.30656296487637653f, 1.0f, 0.54119610014619701f,
                             0.0f, -0.54119610014619701f};
        #pragma unroll
        for (int e = 0; e < 8; e++) {
            float o = c4[e] * v1;
            sm[swz(ub | e)]       = v0 + o;
            sm[swz(ub | (e + 8))] = v0 - o;
        }
    }
    __syncthreads();

    float r[16];
    phaseB(sm, r, t);
    __syncthreads();

    {
        CTw w = ctw(t);
        #pragma unroll
        for (int s = 0; s < 16; s++) r[s] = sm[swz((s << 9) | t)];
        #pragma unroll
        for (int s = 0; s < 16; s += 2) {
            float o = w.c10 * r[s + 1]; r[s + 1] = r[s] - o; r[s] += o;
        }
        {
            const float w11[2] = { w.c11p, w.c11m };
            #pragma unroll
            for (int g = 0; g < 16; g += 4)
                #pragma unroll
                for (int sb = 0; sb < 2; sb++) {
                    int s = g + sb;
                    float o = w11[sb] * r[s + 2]; r[s + 2] = r[s] - o; r[s] += o;
                }
        }
        {
            const float w12[4] = { w.c12p, RSQ2 * (w.c12p + w.c12m),
                                   w.c12m, RSQ2 * (w.c12m - w.c12p) };
            #pragma unroll
            for (int g = 0; g < 16; g += 8)
                #pragma unroll
                for (int sb = 0; sb < 4; sb++) {
                    int s = g + sb;
                    float o = w12[sb] * r[s + 4]; r[s + 4] = r[s] - o; r[s] += o;
                }
        }
        {
            const float CS[8] = {1.0f, C8L, RSQ2, S8L, 0.0f, -S8L, -RSQ2, -C8L};
            const float SN[8] = {0.0f, S8L, RSQ2, C8L, 1.0f,  C8L,  RSQ2,  S8L};
            #pragma unroll
            for (int s = 0; s < 8; s++) {
                float w13 = CS[s] * w.c13p + SN[s] * w.c13m;
                float o = w13 * r[s + 8]; r[s + 8] = r[s] - o; r[s] += o;
            }
        }
        const float scale = 1.0f / (float)NLEN;
        float* __restrict__ orow = out + (size_t)row * NLEN;
        #pragma unroll
        for (int s = 0; s < 16; s++)
            orow[(s << 9) | t] = r[s] * scale;
    }
}

// -------- float4 32x32 transpose: src[R][C] -> dst[C][R] --------------------
__global__ __launch_bounds__(256) void transpose4_kernel(const float* __restrict__ src,
                                                         float* __restrict__ dst,
                                                         int R, int C) {
    __shared__ float tile[32][33];
    const int c0 = blockIdx.x * 32, r0 = blockIdx.y * 32;
    const int tid = threadIdx.x;
    const int tx = tid & 7, ty = tid >> 3;

    float4 v = *(const float4*)&src[(size_t)(r0 + ty) * C + c0 + 4 * tx];
    tile[ty][4*tx + 0] = v.x;
    tile[ty][4*tx + 1] = v.y;
    tile[ty][4*tx + 2] = v.z;
    tile[ty][4*tx + 3] = v.w;
    __syncthreads();

    float4 o;
    o.x = tile[4*tx + 0][ty];
    o.y = tile[4*tx + 1][ty];
    o.z = tile[4*tx + 2][ty];
    o.w = tile[4*tx + 3][ty];
    *(float4*)&dst[(size_t)(c0 + ty) * R + r0 + 4 * tx] = o;
}

// -------- paired mode mixing v5: 32KB smem (w only, 0.5 pre-folded) ---------
// a/d loaded directly from L2-resident g_xmT as broadcast LDG.128.
#define MIX_SMEM (2 * CIN * COUT * 4)   // 32768 B

__global__ __launch_bounds__(256) void mix_kernel() {
    extern __shared__ __align__(16) char dynsm[];
    float* w0s = (float*)dynsm;                    // 0.5 * w(m)  [64][64]
    float* w1s = w0s + CIN * COUT;                 // 0.5 * w(mp) [64][64]

    const int m  = blockIdx.x;                 // 0..512
    const int mp = (MODES - m) & (MODES - 1);
    const int tid = threadIdx.x;

    {
        const float4* wm0 = (const float4*)(g_wT + (size_t)m  * (CIN * COUT));
        const float4* wm1 = (const float4*)(g_wT + (size_t)mp * (CIN * COUT));
        #pragma unroll
        for (int t4 = tid; t4 < (CIN * COUT) / 4; t4 += 256) {
            float4 a = wm0[t4], b = wm1[t4];
            a.x *= 0.5f; a.y *= 0.5f; a.z *= 0.5f; a.w *= 0.5f;
            b.x *= 0.5f; b.y *= 0.5f; b.z *= 0.5f; b.w *= 0.5f;
            ((float4*)w0s)[t4] = a;
            ((float4*)w1s)[t4] = b;
        }
    }
    __syncthreads();

    const int b0 = (tid >> 4) * 2;
    const int o0 = (tid & 15) * 4;

    const float* __restrict__ p00 = g_xmT + (size_t)m  * IROWS + b0 * CIN;
    const float* __restrict__ p01 = p00 + CIN;
    const float* __restrict__ p10 = g_xmT + (size_t)mp * IROWS + b0 * CIN;
    const float* __restrict__ p11 = p10 + CIN;

    ull_t A[2][2] = {{0ull, 0ull}, {0ull, 0ull}};
    ull_t B[2][2] = {{0ull, 0ull}, {0ull, 0ull}};

    #pragma unroll 4
    for (int i4 = 0; i4 < CIN; i4 += 4) {
        float4 v00 = *(const float4*)&p00[i4];
        float4 v10 = *(const float4*)&p10[i4];
        float4 v01 = *(const float4*)&p01[i4];
        float4 v11 = *(const float4*)&p11[i4];
        const float* f00 = (const float*)&v00;
        const float* f10 = (const float*)&v10;
        const float* f01 = (const float*)&v01;
        const float* f11 = (const float*)&v11;
        #pragma unroll
        for (int j = 0; j < 4; j++) {
            int i = i4 + j;
            float a0 = f00[j] + f10[j], d0 = f00[j] - f10[j];
            float a1 = f01[j] + f11[j], d1 = f01[j] - f11[j];
            ull_t aa0 = pack2(a0), dd0 = pack2(d0);
            ull_t aa1 = pack2(a1), dd1 = pack2(d1);
            ull_t nd0 = dd0 ^ 0x8000000080000000ull;
            ull_t nd1 = dd1 ^ 0x8000000080000000ull;
            ulonglong2 w0v = *(const ulonglong2*)&w0s[i * COUT + o0];   // LDS.128
            ulonglong2 w1v = *(const ulonglong2*)&w1s[i * COUT + o0];   // LDS.128
            A[0][0] = fma2(aa0, w0v.x, A[0][0]); A[0][0] = fma2(dd0, w1v.x, A[0][0]);
            A[0][1] = fma2(aa0, w0v.y, A[0][1]); A[0][1] = fma2(dd0, w1v.y, A[0][1]);
            A[1][0] = fma2(aa1, w0v.x, A[1][0]); A[1][0] = fma2(dd1, w1v.x, A[1][0]);
            A[1][1] = fma2(aa1, w0v.y, A[1][1]); A[1][1] = fma2(dd1, w1v.y, A[1][1]);
            B[0][0] = fma2(aa0, w1v.x, B[0][0]); B[0][0] = fma2(nd0, w0v.x, B[0][0]);
            B[0][1] = fma2(aa0, w1v.y, B[0][1]); B[0][1] = fma2(nd0, w0v.y, B[0][1]);
            B[1][0] = fma2(aa1, w1v.x, B[1][0]); B[1][0] = fma2(nd1, w0v.x, B[1][0]);
            B[1][1] = fma2(aa1, w1v.y, B[1][1]); B[1][1] = fma2(nd1, w0v.y, B[1][1]);
        }
    }

    float* zr = g_zT + (size_t)m * OROWS;
    #pragma unroll
    for (int bb = 0; bb < 2; bb++) {
        float x0, x1, x2, x3;
        unpack2(A[bb][0], x0, x1);
        unpack2(A[bb][1], x2, x3);
        zr[(b0+bb)*COUT + o0 + 0] = x0; zr[(b0+bb)*COUT + o0 + 1] = x1;
        zr[(b0+bb)*COUT + o0 + 2] = x2; zr[(b0+bb)*COUT + o0 + 3] = x3;
    }
    if (mp != m) {
        float* zp = g_zT + (size_t)mp * OROWS;
        #pragma unroll
        for (int bb = 0; bb < 2; bb++) {
            float x0, x1, x2, x3;
            unpack2(B[bb][0], x0, x1);
            unpack2(B[bb][1], x2, x3);
            zp[(b0+bb)*COUT + o0 + 0] = x0; zp[(b0+bb)*COUT + o0 + 1] = x1;
            zp[(b0+bb)*COUT + o0 + 2] = x2; zp[(b0+bb)*COUT + o0 + 3] = x3;
        }
    }
}

// ---------------------------------------------------------------------------
extern "C" void kernel_launch(void* const* d_in, const int* in_sizes, int n_in,
                              void* d_out, int out_size) {
    const float* x = (const float*)d_in[0];   // [32][64][8192]
    const float* w = (const float*)d_in[1];   // [64][64][1024]
    float* out = (float*)d_out;               // [32][64][8192]

    float* xm  = nullptr; cudaGetSymbolAddress((void**)&xm,  g_xm);
    float* xmT = nullptr; cudaGetSymbolAddress((void**)&xmT, g_xmT);
    float* wT  = nullptr; cudaGetSymbolAddress((void**)&wT,  g_wT);
    float* zT  = nullptr; cudaGetSymbolAddress((void**)&zT,  g_zT);
    float* z   = nullptr; cudaGetSymbolAddress((void**)&z,   g_z);

    cudaFuncSetAttribute(mix_kernel,
                         cudaFuncAttributeMaxDynamicSharedMemorySize, MIX_SMEM);

    fht_fwd_kernel<<<IROWS, 512>>>(x);

    // xm [2048][1024] -> xmT [1024][2048]
    transpose4_kernel<<<dim3(MODES / 32, IROWS / 32), 256>>>(xm, xmT, IROWS, MODES);
    // w  [4096][1024] -> wT  [1024][4096]
    transpose4_kernel<<<dim3(MODES / 32, (CIN * COUT) / 32), 256>>>(w, wT, CIN * COUT, MODES);

    mix_kernel<<<MODES / 2 + 1, 256, MIX_SMEM>>>();   // 513 blocks: m and m' paired

    // zT [1024][2048] -> z [2048][1024]
    transpose4_kernel<<<dim3(OROWS / 32, MODES / 32), 256>>>(zT, z, MODES, OROWS);

    fht_inv_kernel<<<OROWS, 512>>>(out);
}

// round 15
// speedup vs baseline: 1.0211x; 1.0211x over previous
#include <cuda_runtime.h>
#include <cstdint>

// Problem constants
#define NLEN   8192
#define LOGN   13
#define MODES  1024
#define BATCH  32
#define CIN    64
#define COUT   64
#define IROWS  (BATCH*CIN)    // 2048 input rows
#define OROWS  (BATCH*COUT)   // 2048 output rows

// -------- scratch (no allocations allowed; use __device__ globals) --------
__device__ __align__(16) float g_xm  [IROWS*MODES];   // [row=b*64+i][m]
__device__ __align__(16) float g_xmT [MODES*IROWS];   // [m][row]
__device__ __align__(16) float g_wT  [MODES*CIN*COUT];// [m][i*64+o]
__device__ __align__(16) float g_zT  [MODES*OROWS];   // [m][b*64+o]
__device__ __align__(16) float g_z   [OROWS*MODES];   // [row=b*64+o][m]

// GF(2)-linear smem swizzle. k0^=u5^u9, k1^=u6^u10, k2^=u7^u11, k3^=u8, k4^=u8^u12.
__device__ __forceinline__ int swz(int u) {
    int f = ((u >> 5) & 7) ^ ((u >> 9) & 7)
          ^ (((u >> 8) & 1) * 0x18)
          ^ (((u >> 12) & 1) * 0x10);
    return u ^ f;
}
__device__ __forceinline__ int rev9(int t) { return (int)(__brev((unsigned)t) >> 23); }

// Literal cas values
#define RSQ2  0.70710678118654752f
#define C8L   0.92387953251128674f
#define S8L   0.38268343236508977f
#define C16A  0.98078528040323044f   // cos(pi/16)
#define S16A  0.19509032201612827f   // sin(pi/16)
#define C16B  0.83146961230254524f   // cos(3pi/16)
#define S16B  0.55557023301960222f   // sin(3pi/16)
#define THETA0 7.66990393942820615e-4f   // pi/4096
#define PHI0   1.22718463030851251e-2f   // pi/256

// Packed f32x2 helpers (Blackwell)
typedef unsigned long long ull_t;
__device__ __forceinline__ ull_t pack2(float x) {
    ull_t r; asm("mov.b64 %0, {%1, %1};" : "=l"(r) : "f"(x)); return r;
}
__device__ __forceinline__ ull_t fma2(ull_t a, ull_t b, ull_t c) {
    ull_t d; asm("fma.rn.f32x2 %0, %1, %2, %3;" : "=l"(d) : "l"(a), "l"(b), "l"(c));
    return d;
}
__device__ __forceinline__ void unpack2(ull_t v, float& lo, float& hi) {
    asm("mov.b64 {%0, %1}, %2;" : "=f"(lo), "=f"(hi) : "l"(v));
}

// Phase-C twiddles via MUFU + double-angle (no memory traffic).
struct CTw { float c13p, c13m, c12p, c12m, c11p, c11m, c10; };
__device__ __forceinline__ CTw ctw(int t) {
    float s1, c1;
    __sincosf((float)t * THETA0, &s1, &c1);
    CTw w;
    w.c13p = c1 + s1;  w.c13m = c1 - s1;
    float s2 = 2.0f * s1 * c1, c2 = fmaf(-2.0f * s1, s1, 1.0f);
    w.c12p = c2 + s2;  w.c12m = c2 - s2;
    float s4 = 2.0f * s2 * c2, c4 = fmaf(-2.0f * s2, s2, 1.0f);
    w.c11p = c4 + s4;  w.c11m = c4 - s4;
    float s8 = 2.0f * s4 * c4, c8 = fmaf(-2.0f * s4, s4, 1.0f);
    w.c10  = c8 + s8;
    return w;
}

// -------- Phase A stages 1-4: all twiddles are literals ---------------------
__device__ __forceinline__ void stagesA(float r[16]) {
    #pragma unroll
    for (int e = 0; e < 16; e += 2) {
        float o = r[e + 1]; r[e + 1] = r[e] - o; r[e] += o;
    }
    #pragma unroll
    for (int g = 0; g < 16; g += 4)
        #pragma unroll
        for (int e = g; e < g + 2; e++) {
            float o = r[e + 2]; r[e + 2] = r[e] - o; r[e] += o;
        }
    {
        const float c3[4] = {1.0f, 1.41421356237309515f, 1.0f, 0.0f};
        #pragma unroll
        for (int eb = 0; eb < 4; eb++)
            #pragma unroll
            for (int g = 0; g < 16; g += 8) {
                int e = g + eb;
                float o = c3[eb] * r[e + 4]; r[e + 4] = r[e] - o; r[e] += o;
            }
    }
    {
        const float c4[8] = {1.0f, 1.30656296487637653f, 1.41421356237309515f,
                             1.30656296487637653f, 1.0f, 0.54119610014619701f,
                             0.0f, -0.54119610014619701f};
        #pragma unroll
        for (int e = 0; e < 8; e++) {
            float o = c4[e] * r[e + 8]; r[e + 8] = r[e] - o; r[e] += o;
        }
    }
}

// -------- Phase B stages 5-9: ALL twiddles from MUFU + literals -------------
__device__ __forceinline__ void phaseB(float* sm, float r[16], int t) {
    const int wid  = t >> 5;
    const int lane = t & 31;
    const int base = (lane << 8) | wid;

    float s1, c1;
    __sincosf((float)wid * PHI0, &s1, &c1);
    float p1 = c1 + s1, m1 = c1 - s1;
    float s2 = 2.0f * s1 * c1, c2 = fmaf(-2.0f * s1, s1, 1.0f);
    float p2 = c2 + s2, m2 = c2 - s2;
    float s4 = 2.0f * s2 * c2, c4 = fmaf(-2.0f * s2, s2, 1.0f);
    float p4 = c4 + s4, m4 = c4 - s4;
    float s8 = 2.0f * s4 * c4, c8 = fmaf(-2.0f * s4, s4, 1.0f);
    float p8 = c8 + s8, m8 = c8 - s8;
    float s16 = 2.0f * s8 * c8, c16 = fmaf(-2.0f * s8, s8, 1.0f);
    float p16 = c16 + s16;

    #pragma unroll
    for (int s = 0; s < 16; s++) r[s] = sm[swz(base | (s << 4))];
    #pragma unroll
    for (int s = 0; s < 16; s += 2) {
        float o = p16 * r[s + 1]; r[s + 1] = r[s] - o; r[s] += o;
    }
    {
        const float w6[2] = { p8, m8 };
        #pragma unroll
        for (int sb = 0; sb < 2; sb++)
            #pragma unroll
            for (int g = 0; g < 16; g += 4) {
                int s = g + sb;
                float o = w6[sb] * r[s + 2]; r[s + 2] = r[s] - o; r[s] += o;
            }
    }
    {
        const float w7[4] = { p4, RSQ2 * (p4 + m4), m4, RSQ2 * (m4 - p4) };
        #pragma unroll
        for (int sb = 0; sb < 4; sb++)
            #pragma unroll
            for (int g = 0; g < 16; g += 8) {
                int s = g + sb;
                float o = w7[sb] * r[s + 4]; r[s + 4] = r[s] - o; r[s] += o;
            }
    }
    {
        const float CS[8] = {1.0f, C8L, RSQ2, S8L, 0.0f, -S8L, -RSQ2, -C8L};
        const float SN[8] = {0.0f, S8L, RSQ2, C8L, 1.0f,  C8L,  RSQ2,  S8L};
        #pragma unroll
        for (int s = 0; s < 8; s++) {
            float cas = CS[s] * p2 + SN[s] * m2;
            float o = cas * r[s + 8]; r[s + 8] = r[s] - o; r[s] += o;
        }
    }
    {
        const float CS[16] = { 1.0f,  C16A,  C8L,   C16B,  RSQ2,  S16B,  S8L,   S16A,
                               0.0f, -S16A, -S8L,  -S16B, -RSQ2, -C16B, -C8L,  -C16A};
        const float SN[16] = { 0.0f,  S16A,  S8L,   S16B,  RSQ2,  C16B,  C8L,   C16A,
                               1.0f,  C16A,  C8L,   C16B,  RSQ2,  S16B,  S8L,   S16A};
        const bool odd = (lane & 1);
        #pragma unroll
        for (int s = 0; s < 16; s++) {
            float cas = CS[s] * p1 + SN[s] * m1;
            float p = __shfl_xor_sync(0xFFFFFFFFu, r[s], 1);
            r[s] = odd ? (p - cas * r[s]) : fmaf(cas, p, r[s]);
        }
    }
    #pragma unroll
    for (int s = 0; s < 16; s++) sm[swz(base | (s << 4))] = r[s];
}

// -------- forward: x[row][0..8192) -> xm[row][0..1024) ----------------------
__global__ __launch_bounds__(512, 2) void fht_fwd_kernel(const float* __restrict__ x) {
    __shared__ float sm[NLEN];
    const int row = blockIdx.x;
    const int t = threadIdx.x;
    const float* __restrict__ xr = x + (size_t)row * NLEN;

    float r[16];
    {
        const int REV4[16] = {0,8,4,12, 2,10,6,14, 1,9,5,13, 3,11,7,15};
        #pragma unroll
        for (int e = 0; e < 16; e++) r[REV4[e]] = xr[e * 512 + t];
        stagesA(r);
        const int ub = rev9(t) << 4;
        #pragma unroll
        for (int e = 0; e < 16; e++) sm[swz(ub | e)] = r[e];
    }
    __syncthreads();

    phaseB(sm, r, t);
    __syncthreads();

    {
        CTw w = ctw(t);
        #pragma unroll
        for (int s = 0; s < 16; s++) r[s] = sm[swz((s << 9) | t)];
        #pragma unroll
        for (int s = 0; s < 16; s += 2) {
            float o = w.c10 * r[s + 1]; r[s + 1] = r[s] - o; r[s] += o;
        }
        {
            const float w11[2] = { w.c11p, w.c11m };
            #pragma unroll
            for (int g = 0; g < 16; g += 4)
                #pragma unroll
                for (int sb = 0; sb < 2; sb++)
                    r[g + sb] += w11[sb] * r[g + sb + 2];
        }
        {
            const float w12[2] = { w.c12p, RSQ2 * (w.c12p + w.c12m) };
            #pragma unroll
            for (int g = 0; g < 16; g += 8)
                #pragma unroll
                for (int sb = 0; sb < 2; sb++)
                    r[g + sb] += w12[sb] * r[g + sb + 4];
        }
        r[0] += w.c13p * r[8];
        r[1] += (C8L * w.c13p + S8L * w.c13m) * r[9];

        float* __restrict__ xmr = g_xm + (size_t)row * MODES;
        xmr[t]       = r[0];
        xmr[t + 512] = r[1];
    }
}

// -------- inverse: z[row][0..1024) zero-padded -> out[row][0..8192)/8192 ----
__global__ __launch_bounds__(512, 2) void fht_inv_kernel(float* __restrict__ out) {
    __shared__ float sm[NLEN];
    const int row = blockIdx.x;
    const int t = threadIdx.x;
    const float* __restrict__ zr = g_z + (size_t)row * MODES;

    {
        float v0 = zr[t];
        float v1 = zr[t + 512];
        const int ub = rev9(t) << 4;
        const float c4[8] = {1.0f, 1.30656296487637653f, 1.41421356237309515f,
                             1.30656296487637653f, 1.0f, 0.54119610014619701f,
                             0.0f, -0.54119610014619701f};
        #pragma unroll
        for (int e = 0; e < 8; e++) {
            float o = c4[e] * v1;
            sm[swz(ub | e)]       = v0 + o;
            sm[swz(ub | (e + 8))] = v0 - o;
        }
    }
    __syncthreads();

    float r[16];
    phaseB(sm, r, t);
    __syncthreads();

    {
        CTw w = ctw(t);
        #pragma unroll
        for (int s = 0; s < 16; s++) r[s] = sm[swz((s << 9) | t)];
        #pragma unroll
        for (int s = 0; s < 16; s += 2) {
            float o = w.c10 * r[s + 1]; r[s + 1] = r[s] - o; r[s] += o;
        }
        {
            const float w11[2] = { w.c11p, w.c11m };
            #pragma unroll
            for (int g = 0; g < 16; g += 4)
                #pragma unroll
                for (int sb = 0; sb < 2; sb++) {
                    int s = g + sb;
                    float o = w11[sb] * r[s + 2]; r[s + 2] = r[s] - o; r[s] += o;
                }
        }
        {
            const float w12[4] = { w.c12p, RSQ2 * (w.c12p + w.c12m),
                                   w.c12m, RSQ2 * (w.c12m - w.c12p) };
            #pragma unroll
            for (int g = 0; g < 16; g += 8)
                #pragma unroll
                for (int sb = 0; sb < 4; sb++) {
                    int s = g + sb;
                    float o = w12[sb] * r[s + 4]; r[s + 4] = r[s] - o; r[s] += o;
                }
        }
        {
            const float CS[8] = {1.0f, C8L, RSQ2, S8L, 0.0f, -S8L, -RSQ2, -C8L};
            const float SN[8] = {0.0f, S8L, RSQ2, C8L, 1.0f,  C8L,  RSQ2,  S8L};
            #pragma unroll
            for (int s = 0; s < 8; s++) {
                float w13 = CS[s] * w.c13p + SN[s] * w.c13m;
                float o = w13 * r[s + 8]; r[s + 8] = r[s] - o; r[s] += o;
            }
        }
        const float scale = 1.0f / (float)NLEN;
        float* __restrict__ orow = out + (size_t)row * NLEN;
        #pragma unroll
        for (int s = 0; s < 16; s++)
            orow[(s << 9) | t] = r[s] * scale;
    }
}

// -------- float4 32x32 transpose: src[R][C] -> dst[C][R] --------------------
__global__ __launch_bounds__(256) void transpose4_kernel(const float* __restrict__ src,
                                                         float* __restrict__ dst,
                                                         int R, int C) {
    __shared__ float tile[32][33];
    const int c0 = blockIdx.x * 32, r0 = blockIdx.y * 32;
    const int tid = threadIdx.x;
    const int tx = tid & 7, ty = tid >> 3;

    float4 v = *(const float4*)&src[(size_t)(r0 + ty) * C + c0 + 4 * tx];
    tile[ty][4*tx + 0] = v.x;
    tile[ty][4*tx + 1] = v.y;
    tile[ty][4*tx + 2] = v.z;
    tile[ty][4*tx + 3] = v.w;
    __syncthreads();

    float4 o;
    o.x = tile[4*tx + 0][ty];
    o.y = tile[4*tx + 1][ty];
    o.z = tile[4*tx + 2][ty];
    o.w = tile[4*tx + 3][ty];
    *(float4*)&dst[(size_t)(c0 + ty) * R + r0 + 4 * tx] = o;
}

// -------- paired mode mixing v4 (R13 proven) + max-shared carveout ----------
// saa/sdd scalar (inner-loop reads are per-warp broadcasts; pitch 64),
// w via LDS.128.
#define MIX_SMEM (IROWS * 4 * 2 + 2 * CIN * COUT * 4)   // 49152 B

__global__ __launch_bounds__(256) void mix_kernel() {
    extern __shared__ __align__(16) char dynsm[];
    float* saa = (float*)dynsm;                    // [32][64]
    float* sdd = saa + IROWS;                      // [32][64]
    float* w0s = sdd + IROWS;                      // [64][64]
    float* w1s = w0s + CIN * COUT;                 // [64][64]

    const int m  = blockIdx.x;                 // 0..512
    const int mp = (MODES - m) & (MODES - 1);
    const int tid = threadIdx.x;

    const float* xm0 = g_xmT + (size_t)m  * IROWS;
    const float* xm1 = g_xmT + (size_t)mp * IROWS;
    #pragma unroll
    for (int rr = tid; rr < IROWS; rr += 256) {
        float v0 = xm0[rr], v1 = xm1[rr];
        saa[rr] = 0.5f * (v0 + v1);
        sdd[rr] = 0.5f * (v0 - v1);
    }
    {
        const float4* wm0 = (const float4*)(g_wT + (size_t)m  * (CIN * COUT));
        const float4* wm1 = (const float4*)(g_wT + (size_t)mp * (CIN * COUT));
        #pragma unroll
        for (int t4 = tid; t4 < (CIN * COUT) / 4; t4 += 256) {
            ((float4*)w0s)[t4] = wm0[t4];
            ((float4*)w1s)[t4] = wm1[t4];
        }
    }
    __syncthreads();

    const int b0 = (tid >> 4) * 2;
    const int o0 = (tid & 15) * 4;

    ull_t A[2][2] = {{0ull, 0ull}, {0ull, 0ull}};
    ull_t B[2][2] = {{0ull, 0ull}, {0ull, 0ull}};

    #pragma unroll 8
    for (int i = 0; i < CIN; i++) {
        float d0s = sdd[b0 * CIN + i];
        float d1s = sdd[(b0 + 1) * CIN + i];
        ull_t dd0 = pack2(d0s), dd1 = pack2(d1s);
        ull_t nd0 = dd0 ^ 0x8000000080000000ull;
        ull_t nd1 = dd1 ^ 0x8000000080000000ull;
        ull_t aa0 = pack2(saa[b0 * CIN + i]);
        ull_t aa1 = pack2(saa[(b0 + 1) * CIN + i]);
        ulonglong2 w0v = *(const ulonglong2*)&w0s[i * COUT + o0];   // LDS.128
        ulonglong2 w1v = *(const ulonglong2*)&w1s[i * COUT + o0];   // LDS.128
        A[0][0] = fma2(aa0, w0v.x, A[0][0]); A[0][0] = fma2(dd0, w1v.x, A[0][0]);
        A[0][1] = fma2(aa0, w0v.y, A[0][1]); A[0][1] = fma2(dd0, w1v.y, A[0][1]);
        A[1][0] = fma2(aa1, w0v.x, A[1][0]); A[1][0] = fma2(dd1, w1v.x, A[1][0]);
        A[1][1] = fma2(aa1, w0v.y, A[1][1]); A[1][1] = fma2(dd1, w1v.y, A[1][1]);
        B[0][0] = fma2(aa0, w1v.x, B[0][0]); B[0][0] = fma2(nd0, w0v.x, B[0][0]);
        B[0][1] = fma2(aa0, w1v.y, B[0][1]); B[0][1] = fma2(nd0, w0v.y, B[0][1]);
        B[1][0] = fma2(aa1, w1v.x, B[1][0]); B[1][0] = fma2(nd1, w0v.x, B[1][0]);
        B[1][1] = fma2(aa1, w1v.y, B[1][1]); B[1][1] = fma2(nd1, w0v.y, B[1][1]);
    }

    float* zr = g_zT + (size_t)m * OROWS;
    #pragma unroll
    for (int bb = 0; bb < 2; bb++) {
        float x0, x1, x2, x3;
        unpack2(A[bb][0], x0, x1);
        unpack2(A[bb][1], x2, x3);
        zr[(b0+bb)*COUT + o0 + 0] = x0; zr[(b0+bb)*COUT + o0 + 1] = x1;
        zr[(b0+bb)*COUT + o0 + 2] = x2; zr[(b0+bb)*COUT + o0 + 3] = x3;
    }
    if (mp != m) {
        float* zp = g_zT + (size_t)mp * OROWS;
        #pragma unroll
        for (int bb = 0; bb < 2; bb++) {
            float x0, x1, x2, x3;
            unpack2(B[bb][0], x0, x1);
            unpack2(B[bb][1], x2, x3);
            zp[(b0+bb)*COUT + o0 + 0] = x0; zp[(b0+bb)*COUT + o0 + 1] = x1;
            zp[(b0+bb)*COUT + o0 + 2] = x2; zp[(b0+bb)*COUT + o0 + 3] = x3;
        }
    }
}

// ---------------------------------------------------------------------------
extern "C" void kernel_launch(void* const* d_in, const int* in_sizes, int n_in,
                              void* d_out, int out_size) {
    const float* x = (const float*)d_in[0];   // [32][64][8192]
    const float* w = (const float*)d_in[1];   // [64][64][1024]
    float* out = (float*)d_out;               // [32][64][8192]

    float* xm  = nullptr; cudaGetSymbolAddress((void**)&xm,  g_xm);
    float* xmT = nullptr; cudaGetSymbolAddress((void**)&xmT, g_xmT);
    float* wT  = nullptr; cudaGetSymbolAddress((void**)&wT,  g_wT);
    float* zT  = nullptr; cudaGetSymbolAddress((void**)&zT,  g_zT);
    float* z   = nullptr; cudaGetSymbolAddress((void**)&z,   g_z);

    cudaFuncSetAttribute(mix_kernel,
                         cudaFuncAttributeMaxDynamicSharedMemorySize, MIX_SMEM);
    // Request the max L1/shared carveout so 4 blocks x 48KB fit per SM
    cudaFuncSetAttribute(mix_kernel,
                         cudaFuncAttributePreferredSharedMemoryCarveout,
                         cudaSharedmemCarveoutMaxShared);

    fht_fwd_kernel<<<IROWS, 512>>>(x);

    // xm [2048][1024] -> xmT [1024][2048]
    transpose4_kernel<<<dim3(MODES / 32, IROWS / 32), 256>>>(xm, xmT, IROWS, MODES);
    // w  [4096][1024] -> wT  [1024][4096]
    transpose4_kernel<<<dim3(MODES / 32, (CIN * COUT) / 32), 256>>>(w, wT, CIN * COUT, MODES);

    mix_kernel<<<MODES / 2 + 1, 256, MIX_SMEM>>>();   // 513 blocks: m and m' paired

    // zT [1024][2048] -> z [2048][1024]
    transpose4_kernel<<<dim3(OROWS / 32, MODES / 32), 256>>>(zT, z, MODES, OROWS);

    fht_inv_kernel<<<OROWS, 512>>>(out);
}

// round 16
// speedup vs baseline: 1.0454x; 1.0238x over previous
#include <cuda_runtime.h>
#include <cstdint>

// Problem constants
#define NLEN   8192
#define LOGN   13
#define MODES  1024
#define BATCH  32
#define CIN    64
#define COUT   64
#define IROWS  (BATCH*CIN)    // 2048 input rows
#define OROWS  (BATCH*COUT)   // 2048 output rows

// -------- scratch (no allocations allowed; use __device__ globals) --------
__device__ __align__(16) float g_xm  [IROWS*MODES];   // [row=b*64+i][m]
__device__ __align__(16) float g_xmT [MODES*IROWS];   // [m][row]
__device__ __align__(16) float g_wT  [MODES*CIN*COUT];// [m][i*64+o]
__device__ __align__(16) float g_zT  [MODES*OROWS];   // [m][b*64+o]
__device__ __align__(16) float g_z   [OROWS*MODES];   // [row=b*64+o][m]

// GF(2)-linear smem swizzle. k0^=u5^u9, k1^=u6^u10, k2^=u7^u11, k3^=u8, k4^=u8^u12.
__device__ __forceinline__ int swz(int u) {
    int f = ((u >> 5) & 7) ^ ((u >> 9) & 7)
          ^ (((u >> 8) & 1) * 0x18)
          ^ (((u >> 12) & 1) * 0x10);
    return u ^ f;
}
__device__ __forceinline__ int rev9(int t) { return (int)(__brev((unsigned)t) >> 23); }

// Literal cas values
#define RSQ2  0.70710678118654752f
#define C8L   0.92387953251128674f
#define S8L   0.38268343236508977f
#define C16A  0.98078528040323044f   // cos(pi/16)
#define S16A  0.19509032201612827f   // sin(pi/16)
#define C16B  0.83146961230254524f   // cos(3pi/16)
#define S16B  0.55557023301960222f   // sin(3pi/16)
#define THETA0 7.66990393942820615e-4f   // pi/4096
#define PHI0   1.22718463030851251e-2f   // pi/256

// Packed f32x2 helpers (Blackwell)
typedef unsigned long long ull_t;
__device__ __forceinline__ ull_t pack2(float x) {
    ull_t r; asm("mov.b64 %0, {%1, %1};" : "=l"(r) : "f"(x)); return r;
}
__device__ __forceinline__ ull_t fma2(ull_t a, ull_t b, ull_t c) {
    ull_t d; asm("fma.rn.f32x2 %0, %1, %2, %3;" : "=l"(d) : "l"(a), "l"(b), "l"(c));
    return d;
}
__device__ __forceinline__ void unpack2(ull_t v, float& lo, float& hi) {
    asm("mov.b64 {%0, %1}, %2;" : "=f"(lo), "=f"(hi) : "l"(v));
}

// Phase-C twiddles via MUFU + double-angle (no memory traffic).
struct CTw { float c13p, c13m, c12p, c12m, c11p, c11m, c10; };
__device__ __forceinline__ CTw ctw(int t) {
    float s1, c1;
    __sincosf((float)t * THETA0, &s1, &c1);
    CTw w;
    w.c13p = c1 + s1;  w.c13m = c1 - s1;
    float s2 = 2.0f * s1 * c1, c2 = fmaf(-2.0f * s1, s1, 1.0f);
    w.c12p = c2 + s2;  w.c12m = c2 - s2;
    float s4 = 2.0f * s2 * c2, c4 = fmaf(-2.0f * s2, s2, 1.0f);
    w.c11p = c4 + s4;  w.c11m = c4 - s4;
    float s8 = 2.0f * s4 * c4, c8 = fmaf(-2.0f * s4, s4, 1.0f);
    w.c10  = c8 + s8;
    return w;
}

// -------- Phase A stages 1-4: all twiddles are literals ---------------------
__device__ __forceinline__ void stagesA(float r[16]) {
    #pragma unroll
    for (int e = 0; e < 16; e += 2) {
        float o = r[e + 1]; r[e + 1] = r[e] - o; r[e] += o;
    }
    #pragma unroll
    for (int g = 0; g < 16; g += 4)
        #pragma unroll
        for (int e = g; e < g + 2; e++) {
            float o = r[e + 2]; r[e + 2] = r[e] - o; r[e] += o;
        }
    {
        const float c3[4] = {1.0f, 1.41421356237309515f, 1.0f, 0.0f};
        #pragma unroll
        for (int eb = 0; eb < 4; eb++)
            #pragma unroll
            for (int g = 0; g < 16; g += 8) {
                int e = g + eb;
                float o = c3[eb] * r[e + 4]; r[e + 4] = r[e] - o; r[e] += o;
            }
    }
    {
        const float c4[8] = {1.0f, 1.30656296487637653f, 1.41421356237309515f,
                             1.30656296487637653f, 1.0f, 0.54119610014619701f,
                             0.0f, -0.54119610014619701f};
        #pragma unroll
        for (int e = 0; e < 8; e++) {
            float o = c4[e] * r[e + 8]; r[e + 8] = r[e] - o; r[e] += o;
        }
    }
}

// -------- Phase B stages 5-9: ALL twiddles from MUFU + literals -------------
__device__ __forceinline__ void phaseB(float* sm, float r[16], int t) {
    const int wid  = t >> 5;
    const int lane = t & 31;
    const int base = (lane << 8) | wid;

    float s1, c1;
    __sincosf((float)wid * PHI0, &s1, &c1);
    float p1 = c1 + s1, m1 = c1 - s1;
    float s2 = 2.0f * s1 * c1, c2 = fmaf(-2.0f * s1, s1, 1.0f);
    float p2 = c2 + s2, m2 = c2 - s2;
    float s4 = 2.0f * s2 * c2, c4 = fmaf(-2.0f * s2, s2, 1.0f);
    float p4 = c4 + s4, m4 = c4 - s4;
    float s8 = 2.0f * s4 * c4, c8 = fmaf(-2.0f * s4, s4, 1.0f);
    float p8 = c8 + s8, m8 = c8 - s8;
    float s16 = 2.0f * s8 * c8, c16 = fmaf(-2.0f * s8, s8, 1.0f);
    float p16 = c16 + s16;

    #pragma unroll
    for (int s = 0; s < 16; s++) r[s] = sm[swz(base | (s << 4))];
    #pragma unroll
    for (int s = 0; s < 16; s += 2) {
        float o = p16 * r[s + 1]; r[s + 1] = r[s] - o; r[s] += o;
    }
    {
        const float w6[2] = { p8, m8 };
        #pragma unroll
        for (int sb = 0; sb < 2; sb++)
            #pragma unroll
            for (int g = 0; g < 16; g += 4) {
                int s = g + sb;
                float o = w6[sb] * r[s + 2]; r[s + 2] = r[s] - o; r[s] += o;
            }
    }
    {
        const float w7[4] = { p4, RSQ2 * (p4 + m4), m4, RSQ2 * (m4 - p4) };
        #pragma unroll
        for (int sb = 0; sb < 4; sb++)
            #pragma unroll
            for (int g = 0; g < 16; g += 8) {
                int s = g + sb;
                float o = w7[sb] * r[s + 4]; r[s + 4] = r[s] - o; r[s] += o;
            }
    }
    {
        const float CS[8] = {1.0f, C8L, RSQ2, S8L, 0.0f, -S8L, -RSQ2, -C8L};
        const float SN[8] = {0.0f, S8L, RSQ2, C8L, 1.0f,  C8L,  RSQ2,  S8L};
        #pragma unroll
        for (int s = 0; s < 8; s++) {
            float cas = CS[s] * p2 + SN[s] * m2;
            float o = cas * r[s + 8]; r[s + 8] = r[s] - o; r[s] += o;
        }
    }
    {
        const float CS[16] = { 1.0f,  C16A,  C8L,   C16B,  RSQ2,  S16B,  S8L,   S16A,
                               0.0f, -S16A, -S8L,  -S16B, -RSQ2, -C16B, -C8L,  -C16A};
        const float SN[16] = { 0.0f,  S16A,  S8L,   S16B,  RSQ2,  C16B,  C8L,   C16A,
                               1.0f,  C16A,  C8L,   C16B,  RSQ2,  S16B,  S8L,   S16A};
        const bool odd = (lane & 1);
        #pragma unroll
        for (int s = 0; s < 16; s++) {
            float cas = CS[s] * p1 + SN[s] * m1;
            float p = __shfl_xor_sync(0xFFFFFFFFu, r[s], 1);
            r[s] = odd ? (p - cas * r[s]) : fmaf(cas, p, r[s]);
        }
    }
    #pragma unroll
    for (int s = 0; s < 16; s++) sm[swz(base | (s << 4))] = r[s];
}

// -------- forward: x[row][0..8192) -> xm[row][0..1024) ----------------------
__global__ __launch_bounds__(512, 2) void fht_fwd_kernel(const float* __restrict__ x) {
    __shared__ float sm[NLEN];
    const int row = blockIdx.x;
    const int t = threadIdx.x;
    const float* __restrict__ xr = x + (size_t)row * NLEN;

    float r[16];
    {
        const int REV4[16] = {0,8,4,12, 2,10,6,14, 1,9,5,13, 3,11,7,15};
        #pragma unroll
        for (int e = 0; e < 16; e++) r[REV4[e]] = xr[e * 512 + t];
        stagesA(r);
        const int ub = rev9(t) << 4;
        #pragma unroll
        for (int e = 0; e < 16; e++) sm[swz(ub | e)] = r[e];
    }
    __syncthreads();

    phaseB(sm, r, t);
    __syncthreads();

    {
        CTw w = ctw(t);
        #pragma unroll
        for (int s = 0; s < 16; s++) r[s] = sm[swz((s << 9) | t)];
        #pragma unroll
        for (int s = 0; s < 16; s += 2) {
            float o = w.c10 * r[s + 1]; r[s + 1] = r[s] - o; r[s] += o;
        }
        {
            const float w11[2] = { w.c11p, w.c11m };
            #pragma unroll
            for (int g = 0; g < 16; g += 4)
                #pragma unroll
                for (int sb = 0; sb < 2; sb++)
                    r[g + sb] += w11[sb] * r[g + sb + 2];
        }
        {
            const float w12[2] = { w.c12p, RSQ2 * (w.c12p + w.c12m) };
            #pragma unroll
            for (int g = 0; g < 16; g += 8)
                #pragma unroll
                for (int sb = 0; sb < 2; sb++)
                    r[g + sb] += w12[sb] * r[g + sb + 4];
        }
        r[0] += w.c13p * r[8];
        r[1] += (C8L * w.c13p + S8L * w.c13m) * r[9];

        float* __restrict__ xmr = g_xm + (size_t)row * MODES;
        xmr[t]       = r[0];
        xmr[t + 512] = r[1];
    }
}

// -------- inverse: z[row][0..1024) zero-padded -> out[row][0..8192)/8192 ----
__global__ __launch_bounds__(512, 2) void fht_inv_kernel(float* __restrict__ out) {
    __shared__ float sm[NLEN];
    const int row = blockIdx.x;
    const int t = threadIdx.x;
    const float* __restrict__ zr = g_z + (size_t)row * MODES;

    {
        float v0 = zr[t];
        float v1 = zr[t + 512];
        const int ub = rev9(t) << 4;
        const float c4[8] = {1.0f, 1.30656296487637653f, 1.41421356237309515f,
                             1.30656296487637653f, 1.0f, 0.54119610014619701f,
                             0.0f, -0.54119610014619701f};
        #pragma unroll
        for (int e = 0; e < 8; e++) {
            float o = c4[e] * v1;
            sm[swz(ub | e)]       = v0 + o;
            sm[swz(ub | (e + 8))] = v0 - o;
        }
    }
    __syncthreads();

    float r[16];
    phaseB(sm, r, t);
    __syncthreads();

    {
        CTw w = ctw(t);
        #pragma unroll
        for (int s = 0; s < 16; s++) r[s] = sm[swz((s << 9) | t)];
        #pragma unroll
        for (int s = 0; s < 16; s += 2) {
            float o = w.c10 * r[s + 1]; r[s + 1] = r[s] - o; r[s] += o;
        }
        {
            const float w11[2] = { w.c11p, w.c11m };
            #pragma unroll
            for (int g = 0; g < 16; g += 4)
                #pragma unroll
                for (int sb = 0; sb < 2; sb++) {
                    int s = g + sb;
                    float o = w11[sb] * r[s + 2]; r[s + 2] = r[s] - o; r[s] += o;
                }
        }
        {
            const float w12[4] = { w.c12p, RSQ2 * (w.c12p + w.c12m),
                                   w.c12m, RSQ2 * (w.c12m - w.c12p) };
            #pragma unroll
            for (int g = 0; g < 16; g += 8)
                #pragma unroll
                for (int sb = 0; sb < 4; sb++) {
                    int s = g + sb;
                    float o = w12[sb] * r[s + 4]; r[s + 4] = r[s] - o; r[s] += o;
                }
        }
        {
            const float CS[8] = {1.0f, C8L, RSQ2, S8L, 0.0f, -S8L, -RSQ2, -C8L};
            const float SN[8] = {0.0f, S8L, RSQ2, C8L, 1.0f,  C8L,  RSQ2,  S8L};
            #pragma unroll
            for (int s = 0; s < 8; s++) {
                float w13 = CS[s] * w.c13p + SN[s] * w.c13m;
                float o = w13 * r[s + 8]; r[s + 8] = r[s] - o; r[s] += o;
            }
        }
        const float scale = 1.0f / (float)NLEN;
        float* __restrict__ orow = out + (size_t)row * NLEN;
        #pragma unroll
        for (int s = 0; s < 16; s++)
            orow[(s << 9) | t] = r[s] * scale;
    }
}

// -------- transpose4x: 4 stacked 32x32 tiles per block (MLP=4) --------------
// Block: cols [c0, c0+32), rows [r0, r0+128) as 4 tiles of 32 rows.
// Load AND store warp patterns are identical to the proven transpose4
// (full 128B sector efficiency both sides); only per-thread MLP changes 1->4.
__global__ __launch_bounds__(256) void transpose4x_kernel(const float* __restrict__ src,
                                                          float* __restrict__ dst,
                                                          int R, int C) {
    __shared__ float tile[4][32][33];
    const int c0 = blockIdx.x * 32, r0 = blockIdx.y * 128;
    const int tid = threadIdx.x;
    const int tx = tid & 7, ty = tid >> 3;

    float4 v[4];
    #pragma unroll
    for (int k = 0; k < 4; k++)
        v[k] = *(const float4*)&src[(size_t)(r0 + 32 * k + ty) * C + c0 + 4 * tx];
    #pragma unroll
    for (int k = 0; k < 4; k++) {
        tile[k][ty][4*tx + 0] = v[k].x;
        tile[k][ty][4*tx + 1] = v[k].y;
        tile[k][ty][4*tx + 2] = v[k].z;
        tile[k][ty][4*tx + 3] = v[k].w;
    }
    __syncthreads();

    #pragma unroll
    for (int k = 0; k < 4; k++) {
        float4 o;
        o.x = tile[k][4*tx + 0][ty];
        o.y = tile[k][4*tx + 1][ty];
        o.z = tile[k][4*tx + 2][ty];
        o.w = tile[k][4*tx + 3][ty];
        *(float4*)&dst[(size_t)(c0 + ty) * R + r0 + 32 * k + 4 * tx] = o;
    }
}

// -------- paired mode mixing v4 (R13 proven) --------------------------------
#define MIX_SMEM (IROWS * 4 * 2 + 2 * CIN * COUT * 4)   // 49152 B

__global__ __launch_bounds__(256) void mix_kernel() {
    extern __shared__ __align__(16) char dynsm[];
    float* saa = (float*)dynsm;                    // [32][64]
    float* sdd = saa + IROWS;                      // [32][64]
    float* w0s = sdd + IROWS;                      // [64][64]
    float* w1s = w0s + CIN * COUT;                 // [64][64]

    const int m  = blockIdx.x;                 // 0..512
    const int mp = (MODES - m) & (MODES - 1);
    const int tid = threadIdx.x;

    const float* xm0 = g_xmT + (size_t)m  * IROWS;
    const float* xm1 = g_xmT + (size_t)mp * IROWS;
    #pragma unroll
    for (int rr = tid; rr < IROWS; rr += 256) {
        float v0 = xm0[rr], v1 = xm1[rr];
        saa[rr] = 0.5f * (v0 + v1);
        sdd[rr] = 0.5f * (v0 - v1);
    }
    {
        const float4* wm0 = (const float4*)(g_wT + (size_t)m  * (CIN * COUT));
        const float4* wm1 = (const float4*)(g_wT + (size_t)mp * (CIN * COUT));
        #pragma unroll
        for (int t4 = tid; t4 < (CIN * COUT) / 4; t4 += 256) {
            ((float4*)w0s)[t4] = wm0[t4];
            ((float4*)w1s)[t4] = wm1[t4];
        }
    }
    __syncthreads();

    const int b0 = (tid >> 4) * 2;
    const int o0 = (tid & 15) * 4;

    ull_t A[2][2] = {{0ull, 0ull}, {0ull, 0ull}};
    ull_t B[2][2] = {{0ull, 0ull}, {0ull, 0ull}};

    #pragma unroll 8
    for (int i = 0; i < CIN; i++) {
        float d0s = sdd[b0 * CIN + i];
        float d1s = sdd[(b0 + 1) * CIN + i];
        ull_t dd0 = pack2(d0s), dd1 = pack2(d1s);
        ull_t nd0 = dd0 ^ 0x8000000080000000ull;
        ull_t nd1 = dd1 ^ 0x8000000080000000ull;
        ull_t aa0 = pack2(saa[b0 * CIN + i]);
        ull_t aa1 = pack2(saa[(b0 + 1) * CIN + i]);
        ulonglong2 w0v = *(const ulonglong2*)&w0s[i * COUT + o0];   // LDS.128
        ulonglong2 w1v = *(const ulonglong2*)&w1s[i * COUT + o0];   // LDS.128
        A[0][0] = fma2(aa0, w0v.x, A[0][0]); A[0][0] = fma2(dd0, w1v.x, A[0][0]);
        A[0][1] = fma2(aa0, w0v.y, A[0][1]); A[0][1] = fma2(dd0, w1v.y, A[0][1]);
        A[1][0] = fma2(aa1, w0v.x, A[1][0]); A[1][0] = fma2(dd1, w1v.x, A[1][0]);
        A[1][1] = fma2(aa1, w0v.y, A[1][1]); A[1][1] = fma2(dd1, w1v.y, A[1][1]);
        B[0][0] = fma2(aa0, w1v.x, B[0][0]); B[0][0] = fma2(nd0, w0v.x, B[0][0]);
        B[0][1] = fma2(aa0, w1v.y, B[0][1]); B[0][1] = fma2(nd0, w0v.y, B[0][1]);
        B[1][0] = fma2(aa1, w1v.x, B[1][0]); B[1][0] = fma2(nd1, w0v.x, B[1][0]);
        B[1][1] = fma2(aa1, w1v.y, B[1][1]); B[1][1] = fma2(nd1, w0v.y, B[1][1]);
    }

    float* zr = g_zT + (size_t)m * OROWS;
    #pragma unroll
    for (int bb = 0; bb < 2; bb++) {
        float x0, x1, x2, x3;
        unpack2(A[bb][0], x0, x1);
        unpack2(A[bb][1], x2, x3);
        zr[(b0+bb)*COUT + o0 + 0] = x0; zr[(b0+bb)*COUT + o0 + 1] = x1;
        zr[(b0+bb)*COUT + o0 + 2] = x2; zr[(b0+bb)*COUT + o0 + 3] = x3;
    }
    if (mp != m) {
        float* zp = g_zT + (size_t)mp * OROWS;
        #pragma unroll
        for (int bb = 0; bb < 2; bb++) {
            float x0, x1, x2, x3;
            unpack2(B[bb][0], x0, x1);
            unpack2(B[bb][1], x2, x3);
            zp[(b0+bb)*COUT + o0 + 0] = x0; zp[(b0+bb)*COUT + o0 + 1] = x1;
            zp[(b0+bb)*COUT + o0 + 2] = x2; zp[(b0+bb)*COUT + o0 + 3] = x3;
        }
    }
}

// ---------------------------------------------------------------------------
extern "C" void kernel_launch(void* const* d_in, const int* in_sizes, int n_in,
                              void* d_out, int out_size) {
    const float* x = (const float*)d_in[0];   // [32][64][8192]
    const float* w = (const float*)d_in[1];   // [64][64][1024]
    float* out = (float*)d_out;               // [32][64][8192]

    float* xm  = nullptr; cudaGetSymbolAddress((void**)&xm,  g_xm);
    float* xmT = nullptr; cudaGetSymbolAddress((void**)&xmT, g_xmT);
    float* wT  = nullptr; cudaGetSymbolAddress((void**)&wT,  g_wT);
    float* zT  = nullptr; cudaGetSymbolAddress((void**)&zT,  g_zT);
    float* z   = nullptr; cudaGetSymbolAddress((void**)&z,   g_z);

    cudaFuncSetAttribute(mix_kernel,
                         cudaFuncAttributeMaxDynamicSharedMemorySize, MIX_SMEM);

    fht_fwd_kernel<<<IROWS, 512>>>(x);

    // xm [2048][1024] -> xmT [1024][2048]
    transpose4x_kernel<<<dim3(MODES / 32, IROWS / 128), 256>>>(xm, xmT, IROWS, MODES);
    // w  [4096][1024] -> wT  [1024][4096]
    transpose4x_kernel<<<dim3(MODES / 32, (CIN * COUT) / 128), 256>>>(w, wT, CIN * COUT, MODES);

    mix_kernel<<<MODES / 2 + 1, 256, MIX_SMEM>>>();   // 513 blocks: m and m' paired

    // zT [1024][2048] -> z [2048][1024]
    transpose4x_kernel<<<dim3(OROWS / 32, MODES / 128), 256>>>(zT, z, MODES, OROWS);

    fht_inv_kernel<<<OROWS, 512>>>(out);
}

// round 17
// speedup vs baseline: 1.0973x; 1.0496x over previous
#include <cuda_runtime.h>
#include <cstdint>

// Problem constants
#define NLEN   8192
#define LOGN   13
#define MODES  1024
#define BATCH  32
#define CIN    64
#define COUT   64
#define IROWS  (BATCH*CIN)    // 2048 input rows
#define OROWS  (BATCH*COUT)   // 2048 output rows

// -------- scratch (no allocations allowed; use __device__ globals) --------
__device__ __align__(16) float g_xm  [IROWS*MODES];   // [row=b*64+i][m]
__device__ __align__(16) float g_xmT [MODES*IROWS];   // [m][row]
__device__ __align__(16) float g_wT  [MODES*CIN*COUT];// [m][i*64+o]
__device__ __align__(16) float g_zT  [MODES*OROWS];   // [m][b*64+o]
__device__ __align__(16) float g_z   [OROWS*MODES];   // [row=b*64+o][m]

// GF(2)-linear smem swizzle. k0^=u5^u9, k1^=u6^u10, k2^=u7^u11, k3^=u8, k4^=u8^u12.
__device__ __forceinline__ int swz(int u) {
    int f = ((u >> 5) & 7) ^ ((u >> 9) & 7)
          ^ (((u >> 8) & 1) * 0x18)
          ^ (((u >> 12) & 1) * 0x10);
    return u ^ f;
}
__device__ __forceinline__ int rev9(int t) { return (int)(__brev((unsigned)t) >> 23); }

// Factored swizzle offsets (GF(2)-linearity of swz):
//   phase B: swz(base | (s<<4))  = swz(base) ^ PB_OFF(s)   (base bits 4..7 == 0)
//   phase C: swz((s<<9) | t)     = (t ^ f_t) ^ PC_OFF(s)   (t < 512)
//   prologue: swz(ub | e)        = swz(ub) ^ e             (ub bits 0..3 == 0, e < 16)
#define PB_OFF(s) (((s) << 4) | ((s) >> 1))
#define PC_OFF(s) (((s) << 9) ^ ((s) & 7) ^ (((s) >> 3) << 4))
__device__ __forceinline__ int pc_base(int t) {
    return t ^ (((t >> 5) & 7) ^ (((t >> 8) & 1) * 0x18));
}

// Literal cas values
#define RSQ2  0.70710678118654752f
#define C8L   0.92387953251128674f
#define S8L   0.38268343236508977f
#define C16A  0.98078528040323044f   // cos(pi/16)
#define S16A  0.19509032201612827f   // sin(pi/16)
#define C16B  0.83146961230254524f   // cos(3pi/16)
#define S16B  0.55557023301960222f   // sin(3pi/16)
#define THETA0 7.66990393942820615e-4f   // pi/4096
#define PHI0   1.22718463030851251e-2f   // pi/256

// Packed f32x2 helpers (Blackwell)
typedef unsigned long long ull_t;
__device__ __forceinline__ ull_t pack2(float x) {
    ull_t r; asm("mov.b64 %0, {%1, %1};" : "=l"(r) : "f"(x)); return r;
}
__device__ __forceinline__ ull_t fma2(ull_t a, ull_t b, ull_t c) {
    ull_t d; asm("fma.rn.f32x2 %0, %1, %2, %3;" : "=l"(d) : "l"(a), "l"(b), "l"(c));
    return d;
}
__device__ __forceinline__ void unpack2(ull_t v, float& lo, float& hi) {
    asm("mov.b64 {%0, %1}, %2;" : "=f"(lo), "=f"(hi) : "l"(v));
}

// Phase-C twiddles via MUFU + double-angle (no memory traffic).
struct CTw { float c13p, c13m, c12p, c12m, c11p, c11m, c10; };
__device__ __forceinline__ CTw ctw(int t) {
    float s1, c1;
    __sincosf((float)t * THETA0, &s1, &c1);
    CTw w;
    w.c13p = c1 + s1;  w.c13m = c1 - s1;
    float s2 = 2.0f * s1 * c1, c2 = fmaf(-2.0f * s1, s1, 1.0f);
    w.c12p = c2 + s2;  w.c12m = c2 - s2;
    float s4 = 2.0f * s2 * c2, c4 = fmaf(-2.0f * s2, s2, 1.0f);
    w.c11p = c4 + s4;  w.c11m = c4 - s4;
    float s8 = 2.0f * s4 * c4, c8 = fmaf(-2.0f * s4, s4, 1.0f);
    w.c10  = c8 + s8;
    return w;
}

// -------- Phase A stages 1-4: all twiddles are literals ---------------------
__device__ __forceinline__ void stagesA(float r[16]) {
    #pragma unroll
    for (int e = 0; e < 16; e += 2) {
        float o = r[e + 1]; r[e + 1] = r[e] - o; r[e] += o;
    }
    #pragma unroll
    for (int g = 0; g < 16; g += 4)
        #pragma unroll
        for (int e = g; e < g + 2; e++) {
            float o = r[e + 2]; r[e + 2] = r[e] - o; r[e] += o;
        }
    {
        const float c3[4] = {1.0f, 1.41421356237309515f, 1.0f, 0.0f};
        #pragma unroll
        for (int eb = 0; eb < 4; eb++)
            #pragma unroll
            for (int g = 0; g < 16; g += 8) {
                int e = g + eb;
                float o = c3[eb] * r[e + 4]; r[e + 4] = r[e] - o; r[e] += o;
            }
    }
    {
        const float c4[8] = {1.0f, 1.30656296487637653f, 1.41421356237309515f,
                             1.30656296487637653f, 1.0f, 0.54119610014619701f,
                             0.0f, -0.54119610014619701f};
        #pragma unroll
        for (int e = 0; e < 8; e++) {
            float o = c4[e] * r[e + 8]; r[e + 8] = r[e] - o; r[e] += o;
        }
    }
}

// -------- Phase B stages 5-9: MUFU twiddles, factored-swizzle addresses -----
__device__ __forceinline__ void phaseB(float* sm, float r[16], int t) {
    const int wid  = t >> 5;
    const int lane = t & 31;
    const int pb = swz((lane << 8) | wid);   // one swz; all accesses = pb ^ const

    float s1, c1;
    __sincosf((float)wid * PHI0, &s1, &c1);
    float p1 = c1 + s1, m1 = c1 - s1;
    float s2 = 2.0f * s1 * c1, c2 = fmaf(-2.0f * s1, s1, 1.0f);
    float p2 = c2 + s2, m2 = c2 - s2;
    float s4 = 2.0f * s2 * c2, c4 = fmaf(-2.0f * s2, s2, 1.0f);
    float p4 = c4 + s4, m4 = c4 - s4;
    float s8 = 2.0f * s4 * c4, c8 = fmaf(-2.0f * s4, s4, 1.0f);
    float p8 = c8 + s8, m8 = c8 - s8;
    float s16 = 2.0f * s8 * c8, c16 = fmaf(-2.0f * s8, s8, 1.0f);
    float p16 = c16 + s16;

    #pragma unroll
    for (int s = 0; s < 16; s++) r[s] = sm[pb ^ PB_OFF(s)];
    #pragma unroll
    for (int s = 0; s < 16; s += 2) {
        float o = p16 * r[s + 1]; r[s + 1] = r[s] - o; r[s] += o;
    }
    {
        const float w6[2] = { p8, m8 };
        #pragma unroll
        for (int sb = 0; sb < 2; sb++)
            #pragma unroll
            for (int g = 0; g < 16; g += 4) {
                int s = g + sb;
                float o = w6[sb] * r[s + 2]; r[s + 2] = r[s] - o; r[s] += o;
            }
    }
    {
        const float w7[4] = { p4, RSQ2 * (p4 + m4), m4, RSQ2 * (m4 - p4) };
        #pragma unroll
        for (int sb = 0; sb < 4; sb++)
            #pragma unroll
            for (int g = 0; g < 16; g += 8) {
                int s = g + sb;
                float o = w7[sb] * r[s + 4]; r[s + 4] = r[s] - o; r[s] += o;
            }
    }
    {
        const float CS[8] = {1.0f, C8L, RSQ2, S8L, 0.0f, -S8L, -RSQ2, -C8L};
        const float SN[8] = {0.0f, S8L, RSQ2, C8L, 1.0f,  C8L,  RSQ2,  S8L};
        #pragma unroll
        for (int s = 0; s < 8; s++) {
            float cas = CS[s] * p2 + SN[s] * m2;
            float o = cas * r[s + 8]; r[s + 8] = r[s] - o; r[s] += o;
        }
    }
    {
        const float CS[16] = { 1.0f,  C16A,  C8L,   C16B,  RSQ2,  S16B,  S8L,   S16A,
                               0.0f, -S16A, -S8L,  -S16B, -RSQ2, -C16B, -C8L,  -C16A};
        const float SN[16] = { 0.0f,  S16A,  S8L,   S16B,  RSQ2,  C16B,  C8L,   C16A,
                               1.0f,  C16A,  C8L,   C16B,  RSQ2,  S16B,  S8L,   S16A};
        const bool odd = (lane & 1);
        #pragma unroll
        for (int s = 0; s < 16; s++) {
            float cas = CS[s] * p1 + SN[s] * m1;
            float p = __shfl_xor_sync(0xFFFFFFFFu, r[s], 1);
            r[s] = odd ? (p - cas * r[s]) : fmaf(cas, p, r[s]);
        }
    }
    #pragma unroll
    for (int s = 0; s < 16; s++) sm[pb ^ PB_OFF(s)] = r[s];
}

// -------- forward: x[row][0..8192) -> xm[row][0..1024) ----------------------
__global__ __launch_bounds__(512, 2) void fht_fwd_kernel(const float* __restrict__ x) {
    __shared__ float sm[NLEN];
    const int row = blockIdx.x;
    const int t = threadIdx.x;
    const float* __restrict__ xr = x + (size_t)row * NLEN;

    float r[16];
    {
        const int REV4[16] = {0,8,4,12, 2,10,6,14, 1,9,5,13, 3,11,7,15};
        #pragma unroll
        for (int e = 0; e < 16; e++) r[REV4[e]] = xr[e * 512 + t];
        stagesA(r);
        const int pu = swz(rev9(t) << 4);    // swz(ub|e) = swz(ub) ^ e
        #pragma unroll
        for (int e = 0; e < 16; e++) sm[pu ^ e] = r[e];
    }
    __syncthreads();

    phaseB(sm, r, t);
    __syncthreads();

    {
        CTw w = ctw(t);
        const int pt = pc_base(t);           // swz((s<<9)|t) = pt ^ PC_OFF(s)
        #pragma unroll
        for (int s = 0; s < 16; s++) r[s] = sm[pt ^ PC_OFF(s)];
        #pragma unroll
        for (int s = 0; s < 16; s += 2) {
            float o = w.c10 * r[s + 1]; r[s + 1] = r[s] - o; r[s] += o;
        }
        {
            const float w11[2] = { w.c11p, w.c11m };
            #pragma unroll
            for (int g = 0; g < 16; g += 4)
                #pragma unroll
                for (int sb = 0; sb < 2; sb++)
                    r[g + sb] += w11[sb] * r[g + sb + 2];
        }
        {
            const float w12[2] = { w.c12p, RSQ2 * (w.c12p + w.c12m) };
            #pragma unroll
            for (int g = 0; g < 16; g += 8)
                #pragma unroll
                for (int sb = 0; sb < 2; sb++)
                    r[g + sb] += w12[sb] * r[g + sb + 4];
        }
        r[0] += w.c13p * r[8];
        r[1] += (C8L * w.c13p + S8L * w.c13m) * r[9];

        float* __restrict__ xmr = g_xm + (size_t)row * MODES;
        xmr[t]       = r[0];
        xmr[t + 512] = r[1];
    }
}

// -------- inverse: z[row][0..1024) zero-padded -> out[row][0..8192)/8192 ----
__global__ __launch_bounds__(512, 2) void fht_inv_kernel(float* __restrict__ out) {
    __shared__ float sm[NLEN];
    const int row = blockIdx.x;
    const int t = threadIdx.x;
    const float* __restrict__ zr = g_z + (size_t)row * MODES;

    {
        float v0 = zr[t];
        float v1 = zr[t + 512];
        const int pu = swz(rev9(t) << 4);    // swz(ub|e) = swz(ub) ^ e
        const float c4[8] = {1.0f, 1.30656296487637653f, 1.41421356237309515f,
                             1.30656296487637653f, 1.0f, 0.54119610014619701f,
                             0.0f, -0.54119610014619701f};
        #pragma unroll
        for (int e = 0; e < 8; e++) {
            float o = c4[e] * v1;
            sm[pu ^ e]       = v0 + o;
            sm[pu ^ e ^ 8]   = v0 - o;
        }
    }
    __syncthreads();

    float r[16];
    phaseB(sm, r, t);
    __syncthreads();

    {
        CTw w = ctw(t);
        const int pt = pc_base(t);
        #pragma unroll
        for (int s = 0; s < 16; s++) r[s] = sm[pt ^ PC_OFF(s)];
        #pragma unroll
        for (int s = 0; s < 16; s += 2) {
            float o = w.c10 * r[s + 1]; r[s + 1] = r[s] - o; r[s] += o;
        }
        {
            const float w11[2] = { w.c11p, w.c11m };
            #pragma unroll
            for (int g = 0; g < 16; g += 4)
                #pragma unroll
                for (int sb = 0; sb < 2; sb++) {
                    int s = g + sb;
                    float o = w11[sb] * r[s + 2]; r[s + 2] = r[s] - o; r[s] += o;
                }
        }
        {
            const float w12[4] = { w.c12p, RSQ2 * (w.c12p + w.c12m),
                                   w.c12m, RSQ2 * (w.c12m - w.c12p) };
            #pragma unroll
            for (int g = 0; g < 16; g += 8)
                #pragma unroll
                for (int sb = 0; sb < 4; sb++) {
                    int s = g + sb;
                    float o = w12[sb] * r[s + 4]; r[s + 4] = r[s] - o; r[s] += o;
                }
        }
        {
            const float CS[8] = {1.0f, C8L, RSQ2, S8L, 0.0f, -S8L, -RSQ2, -C8L};
            const float SN[8] = {0.0f, S8L, RSQ2, C8L, 1.0f,  C8L,  RSQ2,  S8L};
            #pragma unroll
            for (int s = 0; s < 8; s++) {
                float w13 = CS[s] * w.c13p + SN[s] * w.c13m;
                float o = w13 * r[s + 8]; r[s + 8] = r[s] - o; r[s] += o;
            }
        }
        const float scale = 1.0f / (float)NLEN;
        float* __restrict__ orow = out + (size_t)row * NLEN;
        #pragma unroll
        for (int s = 0; s < 16; s++)
            orow[(s << 9) | t] = r[s] * scale;
    }
}

// -------- transpose4x: 4 stacked 32x32 tiles per block (MLP=4) --------------
__global__ __launch_bounds__(256) void transpose4x_kernel(const float* __restrict__ src,
                                                          float* __restrict__ dst,
                                                          int R, int C) {
    __shared__ float tile[4][32][33];
    const int c0 = blockIdx.x * 32, r0 = blockIdx.y * 128;
    const int tid = threadIdx.x;
    const int tx = tid & 7, ty = tid >> 3;

    float4 v[4];
    #pragma unroll
    for (int k = 0; k < 4; k++)
        v[k] = *(const float4*)&src[(size_t)(r0 + 32 * k + ty) * C + c0 + 4 * tx];
    #pragma unroll
    for (int k = 0; k < 4; k++) {
        tile[k][ty][4*tx + 0] = v[k].x;
        tile[k][ty][4*tx + 1] = v[k].y;
        tile[k][ty][4*tx + 2] = v[k].z;
        tile[k][ty][4*tx + 3] = v[k].w;
    }
    __syncthreads();

    #pragma unroll
    for (int k = 0; k < 4; k++) {
        float4 o;
        o.x = tile[k][4*tx + 0][ty];
        o.y = tile[k][4*tx + 1][ty];
        o.z = tile[k][4*tx + 2][ty];
        o.w = tile[k][4*tx + 3][ty];
        *(float4*)&dst[(size_t)(c0 + ty) * R + r0 + 32 * k + 4 * tx] = o;
    }
}

// -------- paired mode mixing v4 (R13 proven) --------------------------------
#define MIX_SMEM (IROWS * 4 * 2 + 2 * CIN * COUT * 4)   // 49152 B

__global__ __launch_bounds__(256) void mix_kernel() {
    extern __shared__ __align__(16) char dynsm[];
    float* saa = (float*)dynsm;                    // [32][64]
    float* sdd = saa + IROWS;                      // [32][64]
    float* w0s = sdd + IROWS;                      // [64][64]
    float* w1s = w0s + CIN * COUT;                 // [64][64]

    const int m  = blockIdx.x;                 // 0..512
    const int mp = (MODES - m) & (MODES - 1);
    const int tid = threadIdx.x;

    const float* xm0 = g_xmT + (size_t)m  * IROWS;
    const float* xm1 = g_xmT + (size_t)mp * IROWS;
    #pragma unroll
    for (int rr = tid; rr < IROWS; rr += 256) {
        float v0 = xm0[rr], v1 = xm1[rr];
        saa[rr] = 0.5f * (v0 + v1);
        sdd[rr] = 0.5f * (v0 - v1);
    }
    {
        const float4* wm0 = (const float4*)(g_wT + (size_t)m  * (CIN * COUT));
        const float4* wm1 = (const float4*)(g_wT + (size_t)mp * (CIN * COUT));
        #pragma unroll
        for (int t4 = tid; t4 < (CIN * COUT) / 4; t4 += 256) {
            ((float4*)w0s)[t4] = wm0[t4];
            ((float4*)w1s)[t4] = wm1[t4];
        }
    }
    __syncthreads();

    const int b0 = (tid >> 4) * 2;
    const int o0 = (tid & 15) * 4;

    ull_t A[2][2] = {{0ull, 0ull}, {0ull, 0ull}};
    ull_t B[2][2] = {{0ull, 0ull}, {0ull, 0ull}};

    #pragma unroll 8
    for (int i = 0; i < CIN; i++) {
        float d0s = sdd[b0 * CIN + i];
        float d1s = sdd[(b0 + 1) * CIN + i];
        ull_t dd0 = pack2(d0s), dd1 = pack2(d1s);
        ull_t nd0 = dd0 ^ 0x8000000080000000ull;
        ull_t nd1 = dd1 ^ 0x8000000080000000ull;
        ull_t aa0 = pack2(saa[b0 * CIN + i]);
        ull_t aa1 = pack2(saa[(b0 + 1) * CIN + i]);
        ulonglong2 w0v = *(const ulonglong2*)&w0s[i * COUT + o0];   // LDS.128
        ulonglong2 w1v = *(const ulonglong2*)&w1s[i * COUT + o0];   // LDS.128
        A[0][0] = fma2(aa0, w0v.x, A[0][0]); A[0][0] = fma2(dd0, w1v.x, A[0][0]);
        A[0][1] = fma2(aa0, w0v.y, A[0][1]); A[0][1] = fma2(dd0, w1v.y, A[0][1]);
        A[1][0] = fma2(aa1, w0v.x, A[1][0]); A[1][0] = fma2(dd1, w1v.x, A[1][0]);
        A[1][1] = fma2(aa1, w0v.y, A[1][1]); A[1][1] = fma2(dd1, w1v.y, A[1][1]);
        B[0][0] = fma2(aa0, w1v.x, B[0][0]); B[0][0] = fma2(nd0, w0v.x, B[0][0]);
        B[0][1] = fma2(aa0, w1v.y, B[0][1]); B[0][1] = fma2(nd0, w0v.y, B[0][1]);
        B[1][0] = fma2(aa1, w1v.x, B[1][0]); B[1][0] = fma2(nd1, w0v.x, B[1][0]);
        B[1][1] = fma2(aa1, w1v.y, B[1][1]); B[1][1] = fma2(nd1, w0v.y, B[1][1]);
    }

    float* zr = g_zT + (size_t)m * OROWS;
    #pragma unroll
    for (int bb = 0; bb < 2; bb++) {
        float x0, x1, x2, x3;
        unpack2(A[bb][0], x0, x1);
        unpack2(A[bb][1], x2, x3);
        zr[(b0+bb)*COUT + o0 + 0] = x0; zr[(b0+bb)*COUT + o0 + 1] = x1;
        zr[(b0+bb)*COUT + o0 + 2] = x2; zr[(b0+bb)*COUT + o0 + 3] = x3;
    }
    if (mp != m) {
        float* zp = g_zT + (size_t)mp * OROWS;
        #pragma unroll
        for (int bb = 0; bb < 2; bb++) {
            float x0, x1, x2, x3;
            unpack2(B[bb][0], x0, x1);
            unpack2(B[bb][1], x2, x3);
            zp[(b0+bb)*COUT + o0 + 0] = x0; zp[(b0+bb)*COUT + o0 + 1] = x1;
            zp[(b0+bb)*COUT + o0 + 2] = x2; zp[(b0+bb)*COUT + o0 + 3] = x3;
        }
    }
}

// ---------------------------------------------------------------------------
extern "C" void kernel_launch(void* const* d_in, const int* in_sizes, int n_in,
                              void* d_out, int out_size) {
    const float* x = (const float*)d_in[0];   // [32][64][8192]
    const float* w = (const float*)d_in[1];   // [64][64][1024]
    float* out = (float*)d_out;               // [32][64][8192]

    float* xm  = nullptr; cudaGetSymbolAddress((void**)&xm,  g_xm);
    float* xmT = nullptr; cudaGetSymbolAddress((void**)&xmT, g_xmT);
    float* wT  = nullptr; cudaGetSymbolAddress((void**)&wT,  g_wT);
    float* zT  = nullptr; cudaGetSymbolAddress((void**)&zT,  g_zT);
    float* z   = nullptr; cudaGetSymbolAddress((void**)&z,   g_z);

    cudaFuncSetAttribute(mix_kernel,
                         cudaFuncAttributeMaxDynamicSharedMemorySize, MIX_SMEM);

    fht_fwd_kernel<<<IROWS, 512>>>(x);

    // xm [2048][1024] -> xmT [1024][2048]
    transpose4x_kernel<<<dim3(MODES / 32, IROWS / 128), 256>>>(xm, xmT, IROWS, MODES);
    // w  [4096][1024] -> wT  [1024][4096]
    transpose4x_kernel<<<dim3(MODES / 32, (CIN * COUT) / 128), 256>>>(w, wT, CIN * COUT, MODES);

    mix_kernel<<<MODES / 2 + 1, 256, MIX_SMEM>>>();   // 513 blocks: m and m' paired

    // zT [1024][2048] -> z [2048][1024]
    transpose4x_kernel<<<dim3(OROWS / 32, MODES / 128), 256>>>(zT, z, MODES, OROWS);

    fht_inv_kernel<<<OROWS, 512>>>(out);
}